// round 10
// baseline (speedup 1.0000x reference)
#include <cuda_runtime.h>
#include <cuda_bf16.h>

// AttWModel — N=1024, L=2048, D=128
// out[n] = sum_l softmax_l( X[n,l]·q[n] ) * ( X[n,l]·v ),  q[n] = W^T z[n]
//
// R10: stream/finalize identical to R8 (best). q-kernel: 128 blocks x 256
// threads, 8 n per block, 4-n register blocking per thread, W via coalesced
// LDG (8 MB total L2 traffic), z via broadcast LDS, unroll 8 for MLP.

#define NB    1024
#define LSEQ  2048
#define DIM   128
#define NW    8
#define NBLK  1184

__device__ float  g_q[NB * DIM];
__device__ float4 g_part[NBLK];     // {Za, Na, Zb, Nb}

// ---------------------------------------------------------------------------
// Kernel 1: q = W^T z.
// ---------------------------------------------------------------------------
__global__ void __launch_bounds__(256) compute_q_kernel(
    const float* __restrict__ z, const float* __restrict__ W)
{
    __shared__ __align__(16) float zs[8 * DIM];   // 4 KB

    const int tid = threadIdx.x;
    const int n0  = blockIdx.x * 8;

    // stage 8 z rows: 1024 floats = 256 float4, one per thread
    reinterpret_cast<float4*>(zs)[tid] =
        reinterpret_cast<const float4*>(z + n0 * DIM)[tid];
    __syncthreads();

    const int d = tid & (DIM - 1);     // output column
    const int h = tid >> 7;            // 0/1 -> n sub-group of 4

    const float* zr0 = zs + (4 * h + 0) * DIM;
    const float* zr1 = zs + (4 * h + 1) * DIM;
    const float* zr2 = zs + (4 * h + 2) * DIM;
    const float* zr3 = zs + (4 * h + 3) * DIM;
    const float* Wp  = W + d;

    float a0 = 0.f, a1 = 0.f, a2 = 0.f, a3 = 0.f;
#pragma unroll 8
    for (int e = 0; e < DIM; e++) {
        const float w = __ldg(Wp + e * DIM);
        a0 = fmaf(zr0[e], w, a0);
        a1 = fmaf(zr1[e], w, a1);
        a2 = fmaf(zr2[e], w, a2);
        a3 = fmaf(zr3[e], w, a3);
    }

    const int nb = n0 + 4 * h;
    g_q[(nb + 0) * DIM + d] = a0;
    g_q[(nb + 1) * DIM + d] = a1;
    g_q[(nb + 2) * DIM + d] = a2;
    g_q[(nb + 3) * DIM + d] = a3;
}

// ---------------------------------------------------------------------------
// Phase worker: rows [r0, r1) of the flattened space, fixed n. (unchanged R8)
// ---------------------------------------------------------------------------
__device__ __forceinline__ void phase_loop(
    const float4* __restrict__ Xf,
    int r0, int r1, int wid, int lane,
    float4 q4, float4 v4, float& Z, float& num)
{
    int j = r0 + wid;
    const float4* p = Xf + (size_t)j * 32 + lane;

#pragma unroll 1
    for (; j + NW < r1; j += 2 * NW, p += 2 * NW * 32) {
        const float4 x0 = __ldcs(p);
        const float4 x1 = __ldcs(p + NW * 32);

        float s0 = x0.x*q4.x + x0.y*q4.y + x0.z*q4.z + x0.w*q4.w;
        float t0 = x0.x*v4.x + x0.y*v4.y + x0.z*v4.z + x0.w*v4.w;
        float s1 = x1.x*q4.x + x1.y*q4.y + x1.z*q4.z + x1.w*q4.w;
        float t1 = x1.x*v4.x + x1.y*v4.y + x1.z*v4.z + x1.w*v4.w;

#pragma unroll
        for (int off = 16; off > 0; off >>= 1) {
            s0 += __shfl_xor_sync(0xffffffffu, s0, off);
            s1 += __shfl_xor_sync(0xffffffffu, s1, off);
        }

        const float p0 = __expf(s0);
        const float p1 = __expf(s1);
        Z   += p0 + p1;
        num  = fmaf(p0, t0, fmaf(p1, t1, num));
    }
    if (j < r1) {
        const float4 x0 = __ldcs(p);
        float s0 = x0.x*q4.x + x0.y*q4.y + x0.z*q4.z + x0.w*q4.w;
        float t0 = x0.x*v4.x + x0.y*v4.y + x0.z*v4.z + x0.w*v4.w;
#pragma unroll
        for (int off = 16; off > 0; off >>= 1)
            s0 += __shfl_xor_sync(0xffffffffu, s0, off);
        const float p0 = __expf(s0);
        Z   += p0;
        num  = fmaf(p0, t0, num);
    }
}

// ---------------------------------------------------------------------------
// Kernel 2: streaming (unchanged R8). Block b: rows [b*65536/37, ...).
// ---------------------------------------------------------------------------
__global__ void __launch_bounds__(NW * 32, 8) attw_stream_kernel(
    const float* __restrict__ X,
    const float* __restrict__ v)
{
    const int bid  = blockIdx.x;
    const int lane = threadIdx.x & 31;
    const int wid  = threadIdx.x >> 5;

    const unsigned R0 = ((unsigned)bid << 16) / 37u;
    const unsigned R1 = (((unsigned)bid + 1u) << 16) / 37u;
    const int n0   = (int)(R0 >> 11);
    const int bRow = (int)min(R1, (unsigned)(n0 + 1) << 11);

    const float4* Xf = reinterpret_cast<const float4*>(X);
    const float4  v4 = reinterpret_cast<const float4*>(v)[lane];

    __shared__ float sZa[NW], sNa[NW], sZb[NW], sNb[NW];

    {
        const float4 q4 = reinterpret_cast<const float4*>(g_q + n0 * DIM)[lane];
        float Z = 0.f, num = 0.f;
        phase_loop(Xf, (int)R0, bRow, wid, lane, q4, v4, Z, num);
#pragma unroll
        for (int off = 16; off > 0; off >>= 1)
            num += __shfl_xor_sync(0xffffffffu, num, off);
        if (lane == 0) { sZa[wid] = Z; sNa[wid] = num; }
    }

    {
        float Z = 0.f, num = 0.f;
        if (bRow < (int)R1) {
            const float4 q4 =
                reinterpret_cast<const float4*>(g_q + (n0 + 1) * DIM)[lane];
            phase_loop(Xf, bRow, (int)R1, wid, lane, q4, v4, Z, num);
#pragma unroll
            for (int off = 16; off > 0; off >>= 1)
                num += __shfl_xor_sync(0xffffffffu, num, off);
        }
        if (lane == 0) { sZb[wid] = Z; sNb[wid] = num; }
    }

    __syncthreads();

    if (threadIdx.x == 0) {
        float Za = 0.f, Na = 0.f, Zb = 0.f, Nb = 0.f;
#pragma unroll
        for (int w = 0; w < NW; w++) {
            Za += sZa[w]; Na += sNa[w];
            Zb += sZb[w]; Nb += sNb[w];
        }
        g_part[bid] = make_float4(Za, Na, Zb, Nb);
    }
}

// ---------------------------------------------------------------------------
// Kernel 3: finalize (unchanged R8).
// ---------------------------------------------------------------------------
__global__ void __launch_bounds__(256) finalize_kernel(float* __restrict__ out)
{
    const int n = blockIdx.x * 256 + threadIdx.x;
    if (n >= NB) return;

    const unsigned rlo = (unsigned)n << 11;
    const unsigned rhi = ((unsigned)(n + 1) << 11) - 1u;
    const unsigned bs  = (37u * rlo + 36u) >> 16;
    const unsigned be  = (37u * rhi + 36u) >> 16;

    float Zt = 0.f, Nt = 0.f;
    for (unsigned b = bs; b <= be; b++) {
        const int n0b = (int)(((b << 16) / 37u) >> 11);
        const float4 pw = g_part[b];
        if (n0b == n)          { Zt += pw.x; Nt += pw.y; }
        else if (n0b + 1 == n) { Zt += pw.z; Nt += pw.w; }
    }
    out[n] = Nt / Zt;
}

extern "C" void kernel_launch(void* const* d_in, const int* in_sizes, int n_in,
                              void* d_out, int out_size)
{
    const float* X = (const float*)d_in[0];
    const float* z = (const float*)d_in[1];
    const float* W = (const float*)d_in[2];
    const float* v = (const float*)d_in[3];
    float* out = (float*)d_out;

    compute_q_kernel<<<NB / 8, 256>>>(z, W);
    attw_stream_kernel<<<NBLK, NW * 32>>>(X, v);
    finalize_kernel<<<(NB + 255) / 256, 256>>>(out);
}

// round 11
// speedup vs baseline: 1.0200x; 1.0200x over previous
#include <cuda_runtime.h>
#include <cuda_bf16.h>

// AttWModel — N=1024, L=2048, D=128
// out[n] = sum_l softmax_l( X[n,l]·q[n] ) * ( X[n,l]·v ),  q[n] = W^T z[n]
//
// R11: stream/finalize identical to R8 (best, 161.9us). q-kernel = R1's
// winning shape (thread-per-(n,d), unroll-4 LDG) widened to 4 n's per block:
// same 4096-warp parallelism, 4x less W L2 traffic.

#define NB    1024
#define LSEQ  2048
#define DIM   128
#define NW    8
#define NBLK  1184

__device__ float  g_q[NB * DIM];
__device__ float4 g_part[NBLK];     // {Za, Na, Zb, Nb}

// ---------------------------------------------------------------------------
// Kernel 1: q = W^T z. 256 blocks x 512 threads; thread (g, d) computes
// q[n0+g][d] with a 4-way unrolled coalesced-LDG loop over e.
// ---------------------------------------------------------------------------
__global__ void __launch_bounds__(512) compute_q_kernel(
    const float* __restrict__ z, const float* __restrict__ W)
{
    __shared__ __align__(16) float zs[4 * DIM];   // 2 KB

    const int tid = threadIdx.x;
    const int n0  = blockIdx.x * 4;

    zs[tid] = z[n0 * DIM + tid];     // 512 floats, one per thread
    __syncthreads();

    const int d = tid & (DIM - 1);
    const int g = tid >> 7;          // 0..3

    const float* zrow = zs + g * DIM;
    float a0 = 0.f, a1 = 0.f, a2 = 0.f, a3 = 0.f;
#pragma unroll
    for (int e = 0; e < DIM; e += 4) {
        a0 = fmaf(zrow[e + 0], W[(e + 0) * DIM + d], a0);
        a1 = fmaf(zrow[e + 1], W[(e + 1) * DIM + d], a1);
        a2 = fmaf(zrow[e + 2], W[(e + 2) * DIM + d], a2);
        a3 = fmaf(zrow[e + 3], W[(e + 3) * DIM + d], a3);
    }
    g_q[(n0 + g) * DIM + d] = (a0 + a1) + (a2 + a3);
}

// ---------------------------------------------------------------------------
// Phase worker: rows [r0, r1) of the flattened space, fixed n. (unchanged R8)
// ---------------------------------------------------------------------------
__device__ __forceinline__ void phase_loop(
    const float4* __restrict__ Xf,
    int r0, int r1, int wid, int lane,
    float4 q4, float4 v4, float& Z, float& num)
{
    int j = r0 + wid;
    const float4* p = Xf + (size_t)j * 32 + lane;

#pragma unroll 1
    for (; j + NW < r1; j += 2 * NW, p += 2 * NW * 32) {
        const float4 x0 = __ldcs(p);
        const float4 x1 = __ldcs(p + NW * 32);

        float s0 = x0.x*q4.x + x0.y*q4.y + x0.z*q4.z + x0.w*q4.w;
        float t0 = x0.x*v4.x + x0.y*v4.y + x0.z*v4.z + x0.w*v4.w;
        float s1 = x1.x*q4.x + x1.y*q4.y + x1.z*q4.z + x1.w*q4.w;
        float t1 = x1.x*v4.x + x1.y*v4.y + x1.z*v4.z + x1.w*v4.w;

#pragma unroll
        for (int off = 16; off > 0; off >>= 1) {
            s0 += __shfl_xor_sync(0xffffffffu, s0, off);
            s1 += __shfl_xor_sync(0xffffffffu, s1, off);
        }

        const float p0 = __expf(s0);
        const float p1 = __expf(s1);
        Z   += p0 + p1;
        num  = fmaf(p0, t0, fmaf(p1, t1, num));
    }
    if (j < r1) {
        const float4 x0 = __ldcs(p);
        float s0 = x0.x*q4.x + x0.y*q4.y + x0.z*q4.z + x0.w*q4.w;
        float t0 = x0.x*v4.x + x0.y*v4.y + x0.z*v4.z + x0.w*v4.w;
#pragma unroll
        for (int off = 16; off > 0; off >>= 1)
            s0 += __shfl_xor_sync(0xffffffffu, s0, off);
        const float p0 = __expf(s0);
        Z   += p0;
        num  = fmaf(p0, t0, num);
    }
}

// ---------------------------------------------------------------------------
// Kernel 2: streaming (unchanged R8). Block b: rows [b*65536/37, ...).
// ---------------------------------------------------------------------------
__global__ void __launch_bounds__(NW * 32, 8) attw_stream_kernel(
    const float* __restrict__ X,
    const float* __restrict__ v)
{
    const int bid  = blockIdx.x;
    const int lane = threadIdx.x & 31;
    const int wid  = threadIdx.x >> 5;

    const unsigned R0 = ((unsigned)bid << 16) / 37u;
    const unsigned R1 = (((unsigned)bid + 1u) << 16) / 37u;
    const int n0   = (int)(R0 >> 11);
    const int bRow = (int)min(R1, (unsigned)(n0 + 1) << 11);

    const float4* Xf = reinterpret_cast<const float4*>(X);
    const float4  v4 = reinterpret_cast<const float4*>(v)[lane];

    __shared__ float sZa[NW], sNa[NW], sZb[NW], sNb[NW];

    {
        const float4 q4 = reinterpret_cast<const float4*>(g_q + n0 * DIM)[lane];
        float Z = 0.f, num = 0.f;
        phase_loop(Xf, (int)R0, bRow, wid, lane, q4, v4, Z, num);
#pragma unroll
        for (int off = 16; off > 0; off >>= 1)
            num += __shfl_xor_sync(0xffffffffu, num, off);
        if (lane == 0) { sZa[wid] = Z; sNa[wid] = num; }
    }

    {
        float Z = 0.f, num = 0.f;
        if (bRow < (int)R1) {
            const float4 q4 =
                reinterpret_cast<const float4*>(g_q + (n0 + 1) * DIM)[lane];
            phase_loop(Xf, bRow, (int)R1, wid, lane, q4, v4, Z, num);
#pragma unroll
            for (int off = 16; off > 0; off >>= 1)
                num += __shfl_xor_sync(0xffffffffu, num, off);
        }
        if (lane == 0) { sZb[wid] = Z; sNb[wid] = num; }
    }

    __syncthreads();

    if (threadIdx.x == 0) {
        float Za = 0.f, Na = 0.f, Zb = 0.f, Nb = 0.f;
#pragma unroll
        for (int w = 0; w < NW; w++) {
            Za += sZa[w]; Na += sNa[w];
            Zb += sZb[w]; Nb += sNb[w];
        }
        g_part[bid] = make_float4(Za, Na, Zb, Nb);
    }
}

// ---------------------------------------------------------------------------
// Kernel 3: finalize (unchanged R8).
// ---------------------------------------------------------------------------
__global__ void __launch_bounds__(256) finalize_kernel(float* __restrict__ out)
{
    const int n = blockIdx.x * 256 + threadIdx.x;
    if (n >= NB) return;

    const unsigned rlo = (unsigned)n << 11;
    const unsigned rhi = ((unsigned)(n + 1) << 11) - 1u;
    const unsigned bs  = (37u * rlo + 36u) >> 16;
    const unsigned be  = (37u * rhi + 36u) >> 16;

    float Zt = 0.f, Nt = 0.f;
    for (unsigned b = bs; b <= be; b++) {
        const int n0b = (int)(((b << 16) / 37u) >> 11);
        const float4 pw = g_part[b];
        if (n0b == n)          { Zt += pw.x; Nt += pw.y; }
        else if (n0b + 1 == n) { Zt += pw.z; Nt += pw.w; }
    }
    out[n] = Nt / Zt;
}

extern "C" void kernel_launch(void* const* d_in, const int* in_sizes, int n_in,
                              void* d_out, int out_size)
{
    const float* X = (const float*)d_in[0];
    const float* z = (const float*)d_in[1];
    const float* W = (const float*)d_in[2];
    const float* v = (const float*)d_in[3];
    float* out = (float*)d_out;

    compute_q_kernel<<<NB / 4, 512>>>(z, W);
    attw_stream_kernel<<<NBLK, NW * 32>>>(X, v);
    finalize_kernel<<<(NB + 255) / 256, 256>>>(out);
}

// round 15
// speedup vs baseline: 1.0254x; 1.0053x over previous
#include <cuda_runtime.h>
#include <cuda_bf16.h>

// AttWModel — N=1024, L=2048, D=128
// out[n] = sum_l softmax_l( X[n,l]·q[n] ) * ( X[n,l]·v ),  q[n] = W^T z[n]
//
// R12: stream/finalize identical to R8 (best). q-kernel keeps 4096 warps but
// vectorizes W to LDG.128 via e-range splitting (4 quarters/thread-group),
// partials merged in smem. 4x fewer LSU issues than R11.

#define NB    1024
#define LSEQ  2048
#define DIM   128
#define NW    8
#define NBLK  1184

__device__ float  g_q[NB * DIM];
__device__ float4 g_part[NBLK];     // {Za, Na, Zb, Nb}

// ---------------------------------------------------------------------------
// Kernel 1: q = W^T z. 256 blocks x 512 threads, 4 n's per block.
// Thread (g, qt, d4): float4 partial of q[n0+g][4*d4..4*d4+3] over the
// e-quarter [32*qt, 32*qt+32). 32 x LDG.128 of W, broadcast LDS of z.
// qt==0 threads merge the 4 partials from smem and store.
// ---------------------------------------------------------------------------
__global__ void __launch_bounds__(512) compute_q_kernel(
    const float* __restrict__ z, const float* __restrict__ W)
{
    __shared__ __align__(16) float  zs[4 * DIM];   // 2 KB
    __shared__ __align__(16) float4 qp[512];       // 8 KB partials

    const int tid = threadIdx.x;
    const int n0  = blockIdx.x * 4;

    zs[tid] = z[n0 * DIM + tid];     // 512 floats, one per thread
    __syncthreads();

    const int g  = tid >> 7;         // 0..3  n index in block
    const int t  = tid & 127;
    const int d4 = t & 31;           // float4 column group
    const int qt = t >> 5;           // 0..3  e-quarter

    const float*  zrow = zs + g * DIM + qt * 32;
    const float4* W4   = reinterpret_cast<const float4*>(W)
                       + (size_t)(qt * 32) * 32 + d4;

    float4 a = make_float4(0.f, 0.f, 0.f, 0.f);
#pragma unroll
    for (int e = 0; e < 32; e++) {
        const float4 w = W4[e * 32];
        const float  f = zrow[e];
        a.x = fmaf(f, w.x, a.x);
        a.y = fmaf(f, w.y, a.y);
        a.z = fmaf(f, w.z, a.z);
        a.w = fmaf(f, w.w, a.w);
    }
    qp[tid] = a;
    __syncthreads();

    if (qt == 0) {   // 32 threads per g merge the 4 quarter-partials
        const float4 b0 = qp[tid];
        const float4 b1 = qp[tid + 32];
        const float4 b2 = qp[tid + 64];
        const float4 b3 = qp[tid + 96];
        float4 r;
        r.x = (b0.x + b1.x) + (b2.x + b3.x);
        r.y = (b0.y + b1.y) + (b2.y + b3.y);
        r.z = (b0.z + b1.z) + (b2.z + b3.z);
        r.w = (b0.w + b1.w) + (b2.w + b3.w);
        reinterpret_cast<float4*>(g_q + (n0 + g) * DIM)[d4] = r;
    }
}

// ---------------------------------------------------------------------------
// Phase worker: rows [r0, r1) of the flattened space, fixed n. (unchanged R8)
// ---------------------------------------------------------------------------
__device__ __forceinline__ void phase_loop(
    const float4* __restrict__ Xf,
    int r0, int r1, int wid, int lane,
    float4 q4, float4 v4, float& Z, float& num)
{
    int j = r0 + wid;
    const float4* p = Xf + (size_t)j * 32 + lane;

#pragma unroll 1
    for (; j + NW < r1; j += 2 * NW, p += 2 * NW * 32) {
        const float4 x0 = __ldcs(p);
        const float4 x1 = __ldcs(p + NW * 32);

        float s0 = x0.x*q4.x + x0.y*q4.y + x0.z*q4.z + x0.w*q4.w;
        float t0 = x0.x*v4.x + x0.y*v4.y + x0.z*v4.z + x0.w*v4.w;
        float s1 = x1.x*q4.x + x1.y*q4.y + x1.z*q4.z + x1.w*q4.w;
        float t1 = x1.x*v4.x + x1.y*v4.y + x1.z*v4.z + x1.w*v4.w;

#pragma unroll
        for (int off = 16; off > 0; off >>= 1) {
            s0 += __shfl_xor_sync(0xffffffffu, s0, off);
            s1 += __shfl_xor_sync(0xffffffffu, s1, off);
        }

        const float p0 = __expf(s0);
        const float p1 = __expf(s1);
        Z   += p0 + p1;
        num  = fmaf(p0, t0, fmaf(p1, t1, num));
    }
    if (j < r1) {
        const float4 x0 = __ldcs(p);
        float s0 = x0.x*q4.x + x0.y*q4.y + x0.z*q4.z + x0.w*q4.w;
        float t0 = x0.x*v4.x + x0.y*v4.y + x0.z*v4.z + x0.w*v4.w;
#pragma unroll
        for (int off = 16; off > 0; off >>= 1)
            s0 += __shfl_xor_sync(0xffffffffu, s0, off);
        const float p0 = __expf(s0);
        Z   += p0;
        num  = fmaf(p0, t0, num);
    }
}

// ---------------------------------------------------------------------------
// Kernel 2: streaming (unchanged R8). Block b: rows [b*65536/37, ...).
// ---------------------------------------------------------------------------
__global__ void __launch_bounds__(NW * 32, 8) attw_stream_kernel(
    const float* __restrict__ X,
    const float* __restrict__ v)
{
    const int bid  = blockIdx.x;
    const int lane = threadIdx.x & 31;
    const int wid  = threadIdx.x >> 5;

    const unsigned R0 = ((unsigned)bid << 16) / 37u;
    const unsigned R1 = (((unsigned)bid + 1u) << 16) / 37u;
    const int n0   = (int)(R0 >> 11);
    const int bRow = (int)min(R1, (unsigned)(n0 + 1) << 11);

    const float4* Xf = reinterpret_cast<const float4*>(X);
    const float4  v4 = reinterpret_cast<const float4*>(v)[lane];

    __shared__ float sZa[NW], sNa[NW], sZb[NW], sNb[NW];

    {
        const float4 q4 = reinterpret_cast<const float4*>(g_q + n0 * DIM)[lane];
        float Z = 0.f, num = 0.f;
        phase_loop(Xf, (int)R0, bRow, wid, lane, q4, v4, Z, num);
#pragma unroll
        for (int off = 16; off > 0; off >>= 1)
            num += __shfl_xor_sync(0xffffffffu, num, off);
        if (lane == 0) { sZa[wid] = Z; sNa[wid] = num; }
    }

    {
        float Z = 0.f, num = 0.f;
        if (bRow < (int)R1) {
            const float4 q4 =
                reinterpret_cast<const float4*>(g_q + (n0 + 1) * DIM)[lane];
            phase_loop(Xf, bRow, (int)R1, wid, lane, q4, v4, Z, num);
#pragma unroll
            for (int off = 16; off > 0; off >>= 1)
                num += __shfl_xor_sync(0xffffffffu, num, off);
        }
        if (lane == 0) { sZb[wid] = Z; sNb[wid] = num; }
    }

    __syncthreads();

    if (threadIdx.x == 0) {
        float Za = 0.f, Na = 0.f, Zb = 0.f, Nb = 0.f;
#pragma unroll
        for (int w = 0; w < NW; w++) {
            Za += sZa[w]; Na += sNa[w];
            Zb += sZb[w]; Nb += sNb[w];
        }
        g_part[bid] = make_float4(Za, Na, Zb, Nb);
    }
}

// ---------------------------------------------------------------------------
// Kernel 3: finalize (unchanged R8).
// ---------------------------------------------------------------------------
__global__ void __launch_bounds__(256) finalize_kernel(float* __restrict__ out)
{
    const int n = blockIdx.x * 256 + threadIdx.x;
    if (n >= NB) return;

    const unsigned rlo = (unsigned)n << 11;
    const unsigned rhi = ((unsigned)(n + 1) << 11) - 1u;
    const unsigned bs  = (37u * rlo + 36u) >> 16;
    const unsigned be  = (37u * rhi + 36u) >> 16;

    float Zt = 0.f, Nt = 0.f;
    for (unsigned b = bs; b <= be; b++) {
        const int n0b = (int)(((b << 16) / 37u) >> 11);
        const float4 pw = g_part[b];
        if (n0b == n)          { Zt += pw.x; Nt += pw.y; }
        else if (n0b + 1 == n) { Zt += pw.z; Nt += pw.w; }
    }
    out[n] = Nt / Zt;
}

extern "C" void kernel_launch(void* const* d_in, const int* in_sizes, int n_in,
                              void* d_out, int out_size)
{
    const float* X = (const float*)d_in[0];
    const float* z = (const float*)d_in[1];
    const float* W = (const float*)d_in[2];
    const float* v = (const float*)d_in[3];
    float* out = (float*)d_out;

    compute_q_kernel<<<NB / 4, 512>>>(z, W);
    attw_stream_kernel<<<NBLK, NW * 32>>>(X, v);
    finalize_kernel<<<(NB + 255) / 256, 256>>>(out);
}

// round 16
// speedup vs baseline: 1.0266x; 1.0012x over previous
#include <cuda_runtime.h>
#include <cuda_bf16.h>

// AttWModel — N=1024, L=2048, D=128
// out[n] = sum_l softmax_l( X[n,l]·q[n] ) * ( X[n,l]·v ),  q[n] = W^T z[n]
//
// R16: SINGLE kernel. 1184 blocks (148 SMs x 8), flattened homogeneous row
// partition (R8). Per-block prologue computes the two needed q rows
// (W L1-shared across co-resident blocks); last-block-done runs finalize.

#define NB    1024
#define LSEQ  2048
#define DIM   128
#define NW    8
#define NBLK  1184

__device__ float4       g_part[NBLK];   // {Za, Na, Zb, Nb}
__device__ unsigned int g_done;          // zero-init; reset by finalizing block

// ---------------------------------------------------------------------------
// Phase worker: rows [r0, r1) of the flattened space, fixed n. (unchanged R8)
// ---------------------------------------------------------------------------
__device__ __forceinline__ void phase_loop(
    const float4* __restrict__ Xf,
    int r0, int r1, int wid, int lane,
    float4 q4, float4 v4, float& Z, float& num)
{
    int j = r0 + wid;
    const float4* p = Xf + (size_t)j * 32 + lane;

#pragma unroll 1
    for (; j + NW < r1; j += 2 * NW, p += 2 * NW * 32) {
        const float4 x0 = __ldcs(p);
        const float4 x1 = __ldcs(p + NW * 32);

        float s0 = x0.x*q4.x + x0.y*q4.y + x0.z*q4.z + x0.w*q4.w;
        float t0 = x0.x*v4.x + x0.y*v4.y + x0.z*v4.z + x0.w*v4.w;
        float s1 = x1.x*q4.x + x1.y*q4.y + x1.z*q4.z + x1.w*q4.w;
        float t1 = x1.x*v4.x + x1.y*v4.y + x1.z*v4.z + x1.w*v4.w;

#pragma unroll
        for (int off = 16; off > 0; off >>= 1) {
            s0 += __shfl_xor_sync(0xffffffffu, s0, off);
            s1 += __shfl_xor_sync(0xffffffffu, s1, off);
        }

        const float p0 = __expf(s0);
        const float p1 = __expf(s1);
        Z   += p0 + p1;
        num  = fmaf(p0, t0, fmaf(p1, t1, num));
    }
    if (j < r1) {
        const float4 x0 = __ldcs(p);
        float s0 = x0.x*q4.x + x0.y*q4.y + x0.z*q4.z + x0.w*q4.w;
        float t0 = x0.x*v4.x + x0.y*v4.y + x0.z*v4.z + x0.w*v4.w;
#pragma unroll
        for (int off = 16; off > 0; off >>= 1)
            s0 += __shfl_xor_sync(0xffffffffu, s0, off);
        const float p0 = __expf(s0);
        Z   += p0;
        num  = fmaf(p0, t0, num);
    }
}

// ---------------------------------------------------------------------------
// The one kernel.
// ---------------------------------------------------------------------------
__global__ void __launch_bounds__(NW * 32, 8) attw_one_kernel(
    const float* __restrict__ X,      // [NB*LSEQ, DIM]
    const float* __restrict__ z,      // [NB, DIM]
    const float* __restrict__ W,      // [DIM, DIM]
    const float* __restrict__ v,      // [DIM]
    float* __restrict__ out)          // [NB]
{
    const int bid  = blockIdx.x;
    const int tid  = threadIdx.x;
    const int lane = tid & 31;
    const int wid  = tid >> 5;

    const unsigned R0 = ((unsigned)bid << 16) / 37u;
    const unsigned R1 = (((unsigned)bid + 1u) << 16) / 37u;
    const int n0   = (int)(R0 >> 11);
    const int bRow = (int)min(R1, (unsigned)(n0 + 1) << 11);
    const int n1c  = min(n0 + 1, NB - 1);    // clamped (q unused if clamped)

    __shared__ __align__(16) float  zs[2 * DIM];      // 1 KB
    __shared__ __align__(16) float4 qp[NW * 32];      // 4 KB partials
    __shared__ float sZa[NW], sNa[NW], sZb[NW], sNb[NW];
    __shared__ bool  amLast;

    // ---- Prologue: q[n0], q[n1c] = W^T z. warp = (nn = wid&1, eq = wid>>1).
    zs[tid & 255] = (tid < DIM) ? z[n0 * DIM + tid]
                                : z[n1c * DIM + (tid - DIM)];
    __syncthreads();
    {
        const int nn = wid & 1;
        const int eq = wid >> 1;                       // 0..3
        const float*  zrow = zs + nn * DIM + eq * 32;
        const float4* Wp   = reinterpret_cast<const float4*>(W)
                           + (size_t)(eq * 32) * 32 + lane;
        float4 a = make_float4(0.f, 0.f, 0.f, 0.f);
#pragma unroll
        for (int e = 0; e < 32; e++) {
            const float4 w = Wp[e * 32];
            const float  f = zrow[e];
            a.x = fmaf(f, w.x, a.x);
            a.y = fmaf(f, w.y, a.y);
            a.z = fmaf(f, w.z, a.z);
            a.w = fmaf(f, w.w, a.w);
        }
        qp[wid * 32 + lane] = a;
    }
    __syncthreads();

    const float4* Xf = reinterpret_cast<const float4*>(X);
    const float4  v4 = reinterpret_cast<const float4*>(v)[lane];

    // ---- Phase A: n0
    {
        const float4 b0 = qp[0 * 32 + lane], b2 = qp[2 * 32 + lane];
        const float4 b4 = qp[4 * 32 + lane], b6 = qp[6 * 32 + lane];
        float4 q4;
        q4.x = (b0.x + b2.x) + (b4.x + b6.x);
        q4.y = (b0.y + b2.y) + (b4.y + b6.y);
        q4.z = (b0.z + b2.z) + (b4.z + b6.z);
        q4.w = (b0.w + b2.w) + (b4.w + b6.w);

        float Z = 0.f, num = 0.f;
        phase_loop(Xf, (int)R0, bRow, wid, lane, q4, v4, Z, num);
#pragma unroll
        for (int off = 16; off > 0; off >>= 1)
            num += __shfl_xor_sync(0xffffffffu, num, off);
        if (lane == 0) { sZa[wid] = Z; sNa[wid] = num; }
    }

    // ---- Phase B: n0+1 (qp untouched since prologue sync; re-read is safe)
    {
        float Z = 0.f, num = 0.f;
        if (bRow < (int)R1) {
            const float4 b1 = qp[1 * 32 + lane], b3 = qp[3 * 32 + lane];
            const float4 b5 = qp[5 * 32 + lane], b7 = qp[7 * 32 + lane];
            float4 q4;
            q4.x = (b1.x + b3.x) + (b5.x + b7.x);
            q4.y = (b1.y + b3.y) + (b5.y + b7.y);
            q4.z = (b1.z + b3.z) + (b5.z + b7.z);
            q4.w = (b1.w + b3.w) + (b5.w + b7.w);

            phase_loop(Xf, bRow, (int)R1, wid, lane, q4, v4, Z, num);
#pragma unroll
            for (int off = 16; off > 0; off >>= 1)
                num += __shfl_xor_sync(0xffffffffu, num, off);
        }
        if (lane == 0) { sZb[wid] = Z; sNb[wid] = num; }
    }

    __syncthreads();

    if (tid == 0) {
        float Za = 0.f, Na = 0.f, Zb = 0.f, Nb = 0.f;
#pragma unroll
        for (int w = 0; w < NW; w++) {
            Za += sZa[w]; Na += sNa[w];
            Zb += sZb[w]; Nb += sNb[w];
        }
        g_part[bid] = make_float4(Za, Na, Zb, Nb);
        __threadfence();
        amLast = (atomicAdd(&g_done, 1u) == NBLK - 1u);
    }
    __syncthreads();

    // ---- Last block finalizes (fixed-order math -> deterministic)
    if (amLast) {
        __threadfence();
        for (int n = tid; n < NB; n += NW * 32) {
            const unsigned rlo = (unsigned)n << 11;
            const unsigned rhi = ((unsigned)(n + 1) << 11) - 1u;
            const unsigned bs  = (37u * rlo + 36u) >> 16;
            const unsigned be  = (37u * rhi + 36u) >> 16;

            float Zt = 0.f, Nt = 0.f;
            for (unsigned b = bs; b <= be; b++) {
                const int n0b = (int)(((b << 16) / 37u) >> 11);
                const float4 pw = g_part[b];
                if (n0b == n)          { Zt += pw.x; Nt += pw.y; }
                else if (n0b + 1 == n) { Zt += pw.z; Nt += pw.w; }
            }
            out[n] = Nt / Zt;
        }
        __syncthreads();
        if (tid == 0) g_done = 0u;   // reset for next graph replay
    }
}

extern "C" void kernel_launch(void* const* d_in, const int* in_sizes, int n_in,
                              void* d_out, int out_size)
{
    const float* X = (const float*)d_in[0];
    const float* z = (const float*)d_in[1];
    const float* W = (const float*)d_in[2];
    const float* v = (const float*)d_in[3];
    float* out = (float*)d_out;

    attw_one_kernel<<<NBLK, NW * 32>>>(X, z, W, v, out);
}